// round 1
// baseline (speedup 1.0000x reference)
#include <cuda_runtime.h>
#include <math.h>
#include <stdint.h>

// ---------------- problem constants ----------------
#define T_TOK 2048      // B*S tokens
#define HDIM  2048      // hidden
#define FB    8192      // base ffn
#define NE    8         // experts
#define FE    1024      // expert ffn
#define TOPK  2
#define NPAIR (T_TOK * TOPK)

// ---------------- scratch (static __device__, allocation-free) ----------------
__device__ float g_G   [(size_t)T_TOK * FB];   // base gate pre-activation
__device__ float g_Hb  [(size_t)T_TOK * FB];   // base hidden = silu(g)*u
__device__ float g_base[(size_t)T_TOK * HDIM]; // base MLP output
__device__ float g_EG  [(size_t)NPAIR * FE];   // expert gate pre-activation (pair-major)
__device__ float g_HE  [(size_t)NPAIR * FE];   // expert hidden
__device__ float g_pout[(size_t)NPAIR * HDIM]; // expert down output, scaled by w*alpha
__device__ int   g_cnt[NE];
__device__ int   g_off[NE + 1];
__device__ int   g_cur[NE];
__device__ int   g_tokexp[T_TOK * TOPK];
__device__ float g_tokw  [T_TOK * TOPK];       // w * alpha per slot
__device__ int   g_pairtok[NPAIR];             // grouped-by-expert token index
__device__ float g_pairw  [NPAIR];             // grouped w*alpha
__device__ int   g_tokpair[T_TOK * TOPK];      // token -> pair positions
__device__ float g_c[T_TOK];                   // 1 - sum(w*alpha)

// ---------------- small kernels ----------------
__global__ void zero_counts_kernel() {
    int i = threadIdx.x;
    if (i < NE) g_cnt[i] = 0;
}

// one block (8 warps) per token; warp w computes logit for expert w
__global__ void router_kernel(const float* __restrict__ x,
                              const float* __restrict__ rw,
                              const float* __restrict__ alpha) {
    int t = blockIdx.x;
    int tid = threadIdx.x;
    int w = tid >> 5;
    int lane = tid & 31;
    __shared__ float lg[NE];

    float s = 0.f;
    const float* xr = x + (size_t)t * HDIM;
    const float* wr = rw + (size_t)w * HDIM;
    for (int h = lane; h < HDIM; h += 32) s += xr[h] * wr[h];
    #pragma unroll
    for (int o = 16; o > 0; o >>= 1) s += __shfl_down_sync(0xffffffffu, s, o);
    if (lane == 0) lg[w] = s;
    __syncthreads();

    if (tid == 0) {
        float v0 = -1e30f, v1 = -1e30f;
        int i0 = 0, i1 = 0;
        #pragma unroll
        for (int e = 0; e < NE; e++) {
            float v = lg[e];
            if (v > v0) { v1 = v0; i1 = i0; v0 = v; i0 = e; }
            else if (v > v1) { v1 = v; i1 = e; }
        }
        // softmax over the two selected logits (v0 >= v1)
        float e1 = expf(v1 - v0);
        float inv = 1.f / (1.f + e1);
        float w0 = inv, w1 = e1 * inv;
        float wa0 = w0 * alpha[i0];
        float wa1 = w1 * alpha[i1];
        g_tokexp[2 * t + 0] = i0;
        g_tokexp[2 * t + 1] = i1;
        g_tokw[2 * t + 0] = wa0;
        g_tokw[2 * t + 1] = wa1;
        g_c[t] = 1.f - wa0 - wa1;
        atomicAdd(&g_cnt[i0], 1);
        atomicAdd(&g_cnt[i1], 1);
    }
}

__global__ void scan_kernel() {
    if (threadIdx.x == 0) {
        int acc = 0;
        for (int e = 0; e < NE; e++) {
            g_off[e] = acc;
            g_cur[e] = acc;
            acc += g_cnt[e];
        }
        g_off[NE] = acc;
    }
}

__global__ void scatter_kernel() {
    int t = blockIdx.x * blockDim.x + threadIdx.x;
    if (t >= T_TOK) return;
    #pragma unroll
    for (int s = 0; s < TOPK; s++) {
        int e = g_tokexp[2 * t + s];
        int pos = atomicAdd(&g_cur[e], 1);
        g_pairtok[pos] = t;
        g_pairw[pos] = g_tokw[2 * t + s];
        g_tokpair[2 * t + s] = pos;
    }
}

// ---------------- generic NT GEMM: C[m, n] = sum_k A[m, k] * B[n, k] ----------------
// MODE 0: C = acc
// MODE 1: C = silu(aux) * acc   (aux same shape/indexing as C)
// MODE 2: C = acc * rowscale[row]
// GROUPED: blockIdx.z selects expert; rows restricted to [off[e], off[e+1]); B += e*N*K
// GATHER: A row index = gidx[global_row]
template <int MODE, bool GROUPED, bool GATHER>
__global__ void __launch_bounds__(256)
gemm_nt(const float* __restrict__ A,
        const float* __restrict__ Bb,
        float* __restrict__ C,
        const float* __restrict__ aux,
        const float* __restrict__ rowscale,
        const int* __restrict__ offs,
        const int* __restrict__ gidx,
        int M, int N, int K) {
    constexpr int BM = 128, BN = 64, BK = 16, TM = 8, TN = 4;
    __shared__ __align__(16) float As[BK][BM + 4];
    __shared__ __align__(16) float Bs[BK][BN + 4];

    int rstart, rend;
    const float* B = Bb;
    if (GROUPED) {
        int e = blockIdx.z;
        rstart = offs[e];
        rend = offs[e + 1];
        B += (size_t)e * N * K;
    } else {
        rstart = 0;
        rend = M;
    }

    int rowBase = rstart + blockIdx.y * BM;
    if (rowBase >= rend) return;
    int colBase = blockIdx.x * BN;

    int tid = threadIdx.x;
    int ty = tid >> 4;        // 0..15
    int tx = tid & 15;        // 0..15
    int rC = ty * TM;         // 0..120
    int cC = tx * TN;         // 0..60

    float acc[TM][TN];
    #pragma unroll
    for (int i = 0; i < TM; i++)
        #pragma unroll
        for (int j = 0; j < TN; j++) acc[i][j] = 0.f;

    for (int k0 = 0; k0 < K; k0 += BK) {
        // load A tile (128 rows x 16 k) : 2 float4 per thread
        #pragma unroll
        for (int i = 0; i < 2; i++) {
            int f = tid + i * 256;
            int r = f >> 2;
            int kq = (f & 3) * 4;
            int grow = rowBase + r;
            float4 v = make_float4(0.f, 0.f, 0.f, 0.f);
            if (grow < rend) {
                int arow = GATHER ? gidx[grow] : grow;
                v = *reinterpret_cast<const float4*>(A + (size_t)arow * K + k0 + kq);
            }
            As[kq + 0][r] = v.x;
            As[kq + 1][r] = v.y;
            As[kq + 2][r] = v.z;
            As[kq + 3][r] = v.w;
        }
        // load B tile (64 rows x 16 k) : 1 float4 per thread
        {
            int r = tid >> 2;
            int kq = (tid & 3) * 4;
            float4 v = *reinterpret_cast<const float4*>(B + (size_t)(colBase + r) * K + k0 + kq);
            Bs[kq + 0][r] = v.x;
            Bs[kq + 1][r] = v.y;
            Bs[kq + 2][r] = v.z;
            Bs[kq + 3][r] = v.w;
        }
        __syncthreads();

        #pragma unroll
        for (int kk = 0; kk < BK; kk++) {
            float4 a0 = *reinterpret_cast<const float4*>(&As[kk][rC]);
            float4 a1 = *reinterpret_cast<const float4*>(&As[kk][rC + 4]);
            float4 b0 = *reinterpret_cast<const float4*>(&Bs[kk][cC]);
            float a[TM] = {a0.x, a0.y, a0.z, a0.w, a1.x, a1.y, a1.z, a1.w};
            float b[TN] = {b0.x, b0.y, b0.z, b0.w};
            #pragma unroll
            for (int i = 0; i < TM; i++)
                #pragma unroll
                for (int j = 0; j < TN; j++) acc[i][j] += a[i] * b[j];
        }
        __syncthreads();
    }

    // epilogue (4-col vectorized)
    #pragma unroll
    for (int i = 0; i < TM; i++) {
        int grow = rowBase + rC + i;
        if (grow >= rend) continue;
        size_t idx = (size_t)grow * N + colBase + cC;
        float4 r;
        if (MODE == 0) {
            r = make_float4(acc[i][0], acc[i][1], acc[i][2], acc[i][3]);
        } else if (MODE == 1) {
            float4 gg = *reinterpret_cast<const float4*>(aux + idx);
            float s0 = gg.x / (1.f + __expf(-gg.x));
            float s1 = gg.y / (1.f + __expf(-gg.y));
            float s2 = gg.z / (1.f + __expf(-gg.z));
            float s3 = gg.w / (1.f + __expf(-gg.w));
            r = make_float4(s0 * acc[i][0], s1 * acc[i][1], s2 * acc[i][2], s3 * acc[i][3]);
        } else {
            float sc = rowscale[grow];
            r = make_float4(sc * acc[i][0], sc * acc[i][1], sc * acc[i][2], sc * acc[i][3]);
        }
        *reinterpret_cast<float4*>(C + idx) = r;
    }
}

// ---------------- combine: out[t] = c[t]*base[t] + pout[p0] + pout[p1] ----------------
__global__ void combine_kernel(float* __restrict__ out) {
    int t = blockIdx.x;
    int i = threadIdx.x;          // 0..511 (H/4)
    int p0 = g_tokpair[2 * t + 0];
    int p1 = g_tokpair[2 * t + 1];
    float ct = g_c[t];
    const float4* b4 = reinterpret_cast<const float4*>(g_base) + (size_t)t * (HDIM / 4);
    const float4* q0 = reinterpret_cast<const float4*>(g_pout) + (size_t)p0 * (HDIM / 4);
    const float4* q1 = reinterpret_cast<const float4*>(g_pout) + (size_t)p1 * (HDIM / 4);
    float4 b = b4[i], a0 = q0[i], a1 = q1[i];
    float4 r;
    r.x = ct * b.x + a0.x + a1.x;
    r.y = ct * b.y + a0.y + a1.y;
    r.z = ct * b.z + a0.z + a1.z;
    r.w = ct * b.w + a0.w + a1.w;
    reinterpret_cast<float4*>(out)[(size_t)t * (HDIM / 4) + i] = r;
}

// ---------------- launch ----------------
extern "C" void kernel_launch(void* const* d_in, const int* in_sizes, int n_in,
                              void* d_out, int out_size) {
    const float* x   = (const float*)d_in[0];  // [T, H]
    const float* wg  = (const float*)d_in[1];  // [FB, H]
    const float* wu  = (const float*)d_in[2];  // [FB, H]
    const float* wd  = (const float*)d_in[3];  // [H, FB]
    const float* rw  = (const float*)d_in[4];  // [E, H]
    const float* weg = (const float*)d_in[5];  // [E, FE, H]
    const float* weu = (const float*)d_in[6];  // [E, FE, H]
    const float* wed = (const float*)d_in[7];  // [E, H, FE]
    const float* alp = (const float*)d_in[8];  // [E]
    float* out = (float*)d_out;

    // device symbol addresses (queries only; no allocation)
    float *pG, *pHb, *pBase, *pEG, *pHE, *pPout, *pPairw;
    int *pOff, *pPairtok;
    cudaGetSymbolAddress((void**)&pG, g_G);
    cudaGetSymbolAddress((void**)&pHb, g_Hb);
    cudaGetSymbolAddress((void**)&pBase, g_base);
    cudaGetSymbolAddress((void**)&pEG, g_EG);
    cudaGetSymbolAddress((void**)&pHE, g_HE);
    cudaGetSymbolAddress((void**)&pPout, g_pout);
    cudaGetSymbolAddress((void**)&pPairw, g_pairw);
    cudaGetSymbolAddress((void**)&pOff, g_off);
    cudaGetSymbolAddress((void**)&pPairtok, g_pairtok);

    // 1) routing
    zero_counts_kernel<<<1, 32>>>();
    router_kernel<<<T_TOK, 256>>>(x, rw, alp);
    scan_kernel<<<1, 1>>>();
    scatter_kernel<<<T_TOK / 256, 256>>>();

    // 2) base MLP
    dim3 gBaseFF(FB / 64, T_TOK / 128, 1);
    gemm_nt<0, false, false><<<gBaseFF, 256>>>(x, wg, pG, nullptr, nullptr, nullptr, nullptr,
                                               T_TOK, FB, HDIM);
    gemm_nt<1, false, false><<<gBaseFF, 256>>>(x, wu, pHb, pG, nullptr, nullptr, nullptr,
                                               T_TOK, FB, HDIM);
    dim3 gBaseDown(HDIM / 64, T_TOK / 128, 1);
    gemm_nt<0, false, false><<<gBaseDown, 256>>>(pHb, wd, pBase, nullptr, nullptr, nullptr, nullptr,
                                                 T_TOK, HDIM, FB);

    // 3) expert MLPs (grouped by expert, gathered rows; max 2048 rows/expert -> 16 row tiles)
    dim3 gExpFF(FE / 64, 16, NE);
    gemm_nt<0, true, true><<<gExpFF, 256>>>(x, weg, pEG, nullptr, nullptr, pOff, pPairtok,
                                            NPAIR, FE, HDIM);
    gemm_nt<1, true, true><<<gExpFF, 256>>>(x, weu, pHE, pEG, nullptr, pOff, pPairtok,
                                            NPAIR, FE, HDIM);
    dim3 gExpDown(HDIM / 64, 16, NE);
    gemm_nt<2, true, false><<<gExpDown, 256>>>(pHE, wed, pPout, nullptr, pPairw, pOff, nullptr,
                                               NPAIR, HDIM, FE);

    // 4) combine
    combine_kernel<<<T_TOK, HDIM / 4>>>(out);
}

// round 3
// speedup vs baseline: 3.0447x; 3.0447x over previous
#include <cuda_runtime.h>
#include <math.h>
#include <stdint.h>

// ---------------- problem constants ----------------
#define T_TOK 2048
#define HDIM  2048
#define FB    8192
#define NE    8
#define FE    1024
#define TOPK  2
#define NPAIR (T_TOK * TOPK)

// ---------------- scratch ----------------
__device__ float g_G   [(size_t)T_TOK * FB];
__device__ float g_Hb  [(size_t)T_TOK * FB];
__device__ float g_base[(size_t)T_TOK * HDIM];
__device__ float g_EG  [(size_t)NPAIR * FE];
__device__ float g_HE  [(size_t)NPAIR * FE];
__device__ float g_pout[(size_t)NPAIR * HDIM];
__device__ int   g_cnt[NE];
__device__ int   g_off[NE + 1];
__device__ int   g_cur[NE];
__device__ int   g_tokexp[T_TOK * TOPK];
__device__ float g_tokw  [T_TOK * TOPK];
__device__ int   g_pairtok[NPAIR];
__device__ float g_pairw  [NPAIR];
__device__ int   g_tokpair[T_TOK * TOPK];
__device__ float g_c[T_TOK];

// ---------------- small kernels (fp32-exact routing) ----------------
__global__ void zero_counts_kernel() {
    int i = threadIdx.x;
    if (i < NE) g_cnt[i] = 0;
}

__global__ void router_kernel(const float* __restrict__ x,
                              const float* __restrict__ rw,
                              const float* __restrict__ alpha) {
    int t = blockIdx.x;
    int tid = threadIdx.x;
    int w = tid >> 5;
    int lane = tid & 31;
    __shared__ float lg[NE];

    float s = 0.f;
    const float* xr = x + (size_t)t * HDIM;
    const float* wr = rw + (size_t)w * HDIM;
    for (int h = lane; h < HDIM; h += 32) s += xr[h] * wr[h];
    #pragma unroll
    for (int o = 16; o > 0; o >>= 1) s += __shfl_down_sync(0xffffffffu, s, o);
    if (lane == 0) lg[w] = s;
    __syncthreads();

    if (tid == 0) {
        float v0 = -1e30f, v1 = -1e30f;
        int i0 = 0, i1 = 0;
        #pragma unroll
        for (int e = 0; e < NE; e++) {
            float v = lg[e];
            if (v > v0) { v1 = v0; i1 = i0; v0 = v; i0 = e; }
            else if (v > v1) { v1 = v; i1 = e; }
        }
        float e1 = expf(v1 - v0);
        float inv = 1.f / (1.f + e1);
        float wa0 = inv * alpha[i0];
        float wa1 = e1 * inv * alpha[i1];
        g_tokexp[2 * t + 0] = i0;
        g_tokexp[2 * t + 1] = i1;
        g_tokw[2 * t + 0] = wa0;
        g_tokw[2 * t + 1] = wa1;
        g_c[t] = 1.f - wa0 - wa1;
        atomicAdd(&g_cnt[i0], 1);
        atomicAdd(&g_cnt[i1], 1);
    }
}

__global__ void scan_kernel() {
    if (threadIdx.x == 0) {
        int acc = 0;
        for (int e = 0; e < NE; e++) {
            g_off[e] = acc;
            g_cur[e] = acc;
            acc += g_cnt[e];
        }
        g_off[NE] = acc;
    }
}

__global__ void scatter_kernel() {
    int t = blockIdx.x * blockDim.x + threadIdx.x;
    if (t >= T_TOK) return;
    #pragma unroll
    for (int s = 0; s < TOPK; s++) {
        int e = g_tokexp[2 * t + s];
        int pos = atomicAdd(&g_cur[e], 1);
        g_pairtok[pos] = t;
        g_pairw[pos] = g_tokw[2 * t + s];
        g_tokpair[2 * t + s] = pos;
    }
}

// ---------------- TF32 helpers ----------------
__device__ __forceinline__ uint32_t f2tf32(float f) {
    uint32_t u;
    asm("cvt.rna.tf32.f32 %0, %1;" : "=r"(u) : "f"(f));
    return u;
}

__device__ __forceinline__ void mma_tf32(float c[4], const uint32_t a[4], const uint32_t b[2]) {
    asm volatile(
        "mma.sync.aligned.m16n8k8.row.col.f32.tf32.tf32.f32 "
        "{%0,%1,%2,%3}, {%4,%5,%6,%7}, {%8,%9}, {%0,%1,%2,%3};\n"
        : "+f"(c[0]), "+f"(c[1]), "+f"(c[2]), "+f"(c[3])
        : "r"(a[0]), "r"(a[1]), "r"(a[2]), "r"(a[3]), "r"(b[0]), "r"(b[1]));
}

// ---------------- tensor-core NT GEMM: C[m,n] = sum_k A[m,k]*B[n,k] ----------------
// MODE 0: C = acc; MODE 1: C = silu(aux)*acc; MODE 2: C = acc*rowscale[row]
// GROUPED: blockIdx.z = expert, rows in [off[e], off[e+1]), B += e*N*K
// GATHER:  A row = gidx[global_row]
template <int MODE, bool GROUPED, bool GATHER>
__global__ void __launch_bounds__(256, 2)
gemm_tc(const float* __restrict__ A,
        const float* __restrict__ Bb,
        float* __restrict__ C,
        const float* __restrict__ aux,
        const float* __restrict__ rowscale,
        const int* __restrict__ offs,
        const int* __restrict__ gidx,
        int M, int N, int K) {
    constexpr int BM = 128, BN = 128, BK = 32, SK = BK + 4;  // padded stride: conflict-free frags
    __shared__ uint32_t As[BM * SK];
    __shared__ uint32_t Bs[BN * SK];

    int rstart, rend;
    const float* B = Bb;
    if (GROUPED) {
        int e = blockIdx.z;
        rstart = offs[e];
        rend = offs[e + 1];
        B += (size_t)e * N * K;
    } else {
        rstart = 0;
        rend = M;
    }

    int rowBase = rstart + blockIdx.y * BM;
    if (rowBase >= rend) return;
    int colBase = blockIdx.x * BN;

    int tid = threadIdx.x;
    int wid = tid >> 5, lane = tid & 31;
    int warp_m = wid & 1;        // 2 warps over M
    int warp_n = wid >> 1;       // 4 warps over N
    int g = lane >> 2, tg = lane & 3;

    float acc[4][4][4];          // [mt][nt][reg]
    #pragma unroll
    for (int mt = 0; mt < 4; mt++)
        #pragma unroll
        for (int nt = 0; nt < 4; nt++)
            #pragma unroll
            for (int r = 0; r < 4; r++) acc[mt][nt][r] = 0.f;

    for (int k0 = 0; k0 < K; k0 += BK) {
        // load A tile: 128 rows x 32 k, 4 float4 per thread, convert to tf32
        #pragma unroll
        for (int i = 0; i < 4; i++) {
            int f = tid + i * 256;
            int r = f >> 3;
            int kq = (f & 7) * 4;
            int grow = rowBase + r;
            float4 v = make_float4(0.f, 0.f, 0.f, 0.f);
            if (grow < rend) {
                int ar = GATHER ? gidx[grow] : grow;
                v = *reinterpret_cast<const float4*>(A + (size_t)ar * K + k0 + kq);
            }
            uint32_t* dst = &As[r * SK + kq];
            dst[0] = f2tf32(v.x);
            dst[1] = f2tf32(v.y);
            dst[2] = f2tf32(v.z);
            dst[3] = f2tf32(v.w);
        }
        // load B tile: 128 rows x 32 k
        #pragma unroll
        for (int i = 0; i < 4; i++) {
            int f = tid + i * 256;
            int r = f >> 3;
            int kq = (f & 7) * 4;
            float4 v = *reinterpret_cast<const float4*>(B + (size_t)(colBase + r) * K + k0 + kq);
            uint32_t* dst = &Bs[r * SK + kq];
            dst[0] = f2tf32(v.x);
            dst[1] = f2tf32(v.y);
            dst[2] = f2tf32(v.z);
            dst[3] = f2tf32(v.w);
        }
        __syncthreads();

        #pragma unroll
        for (int ks = 0; ks < BK; ks += 8) {
            uint32_t afr[4][4];
            uint32_t bfr[4][2];
            #pragma unroll
            for (int mt = 0; mt < 4; mt++) {
                int row = warp_m * 64 + mt * 16;
                afr[mt][0] = As[(row + g)     * SK + ks + tg];
                afr[mt][1] = As[(row + g + 8) * SK + ks + tg];
                afr[mt][2] = As[(row + g)     * SK + ks + tg + 4];
                afr[mt][3] = As[(row + g + 8) * SK + ks + tg + 4];
            }
            #pragma unroll
            for (int nt = 0; nt < 4; nt++) {
                int col = warp_n * 32 + nt * 8;
                bfr[nt][0] = Bs[(col + g) * SK + ks + tg];
                bfr[nt][1] = Bs[(col + g) * SK + ks + tg + 4];
            }
            #pragma unroll
            for (int mt = 0; mt < 4; mt++)
                #pragma unroll
                for (int nt = 0; nt < 4; nt++)
                    mma_tf32(acc[mt][nt], afr[mt], bfr[nt]);
        }
        __syncthreads();
    }

    // epilogue: each (mt, nt) fragment -> two rows x float2
    #pragma unroll
    for (int mt = 0; mt < 4; mt++) {
        #pragma unroll
        for (int half = 0; half < 2; half++) {
            int grow = rowBase + warp_m * 64 + mt * 16 + g + half * 8;
            if (grow >= rend) continue;
            float rs = (MODE == 2) ? rowscale[grow] : 0.f;
            #pragma unroll
            for (int nt = 0; nt < 4; nt++) {
                int col = colBase + warp_n * 32 + nt * 8 + tg * 2;
                size_t idx = (size_t)grow * N + col;
                float v0 = acc[mt][nt][half * 2 + 0];
                float v1 = acc[mt][nt][half * 2 + 1];
                float2 r;
                if (MODE == 0) {
                    r = make_float2(v0, v1);
                } else if (MODE == 1) {
                    float2 gg = *reinterpret_cast<const float2*>(aux + idx);
                    float s0 = gg.x / (1.f + __expf(-gg.x));
                    float s1 = gg.y / (1.f + __expf(-gg.y));
                    r = make_float2(s0 * v0, s1 * v1);
                } else {
                    r = make_float2(rs * v0, rs * v1);
                }
                *reinterpret_cast<float2*>(C + idx) = r;
            }
        }
    }
}

// ---------------- combine ----------------
__global__ void combine_kernel(float* __restrict__ out) {
    int t = blockIdx.x;
    int i = threadIdx.x;  // 0..511 (H/4)
    int p0 = g_tokpair[2 * t + 0];
    int p1 = g_tokpair[2 * t + 1];
    float ct = g_c[t];
    const float4* b4 = reinterpret_cast<const float4*>(g_base) + (size_t)t * (HDIM / 4);
    const float4* q0 = reinterpret_cast<const float4*>(g_pout) + (size_t)p0 * (HDIM / 4);
    const float4* q1 = reinterpret_cast<const float4*>(g_pout) + (size_t)p1 * (HDIM / 4);
    float4 b = b4[i], a0 = q0[i], a1 = q1[i];
    float4 r;
    r.x = ct * b.x + a0.x + a1.x;
    r.y = ct * b.y + a0.y + a1.y;
    r.z = ct * b.z + a0.z + a1.z;
    r.w = ct * b.w + a0.w + a1.w;
    reinterpret_cast<float4*>(out)[(size_t)t * (HDIM / 4) + i] = r;
}

// ---------------- launch ----------------
extern "C" void kernel_launch(void* const* d_in, const int* in_sizes, int n_in,
                              void* d_out, int out_size) {
    const float* x   = (const float*)d_in[0];
    const float* wg  = (const float*)d_in[1];
    const float* wu  = (const float*)d_in[2];
    const float* wd  = (const float*)d_in[3];
    const float* rw  = (const float*)d_in[4];
    const float* weg = (const float*)d_in[5];
    const float* weu = (const float*)d_in[6];
    const float* wed = (const float*)d_in[7];
    const float* alp = (const float*)d_in[8];
    float* out = (float*)d_out;

    float *pG, *pHb, *pBase, *pEG, *pHE, *pPout, *pPairw;
    int *pOff, *pPairtok;
    cudaGetSymbolAddress((void**)&pG, g_G);
    cudaGetSymbolAddress((void**)&pHb, g_Hb);
    cudaGetSymbolAddress((void**)&pBase, g_base);
    cudaGetSymbolAddress((void**)&pEG, g_EG);
    cudaGetSymbolAddress((void**)&pHE, g_HE);
    cudaGetSymbolAddress((void**)&pPout, g_pout);
    cudaGetSymbolAddress((void**)&pPairw, g_pairw);
    cudaGetSymbolAddress((void**)&pOff, g_off);
    cudaGetSymbolAddress((void**)&pPairtok, g_pairtok);

    // 1) routing (fp32-exact)
    zero_counts_kernel<<<1, 32>>>();
    router_kernel<<<T_TOK, 256>>>(x, rw, alp);
    scan_kernel<<<1, 1>>>();
    scatter_kernel<<<T_TOK / 256, 256>>>();

    // 2) base MLP (tensor-core TF32)
    dim3 gBaseFF(FB / 128, T_TOK / 128, 1);
    gemm_tc<0, false, false><<<gBaseFF, 256>>>(x, wg, pG, nullptr, nullptr, nullptr, nullptr,
                                               T_TOK, FB, HDIM);
    gemm_tc<1, false, false><<<gBaseFF, 256>>>(x, wu, pHb, pG, nullptr, nullptr, nullptr,
                                               T_TOK, FB, HDIM);
    dim3 gBaseDown(HDIM / 128, T_TOK / 128, 1);
    gemm_tc<0, false, false><<<gBaseDown, 256>>>(pHb, wd, pBase, nullptr, nullptr, nullptr, nullptr,
                                                 T_TOK, HDIM, FB);

    // 3) expert MLPs (grouped, gathered)
    dim3 gExpFF(FE / 128, 16, NE);
    gemm_tc<0, true, true><<<gExpFF, 256>>>(x, weg, pEG, nullptr, nullptr, pOff, pPairtok,
                                            NPAIR, FE, HDIM);
    gemm_tc<1, true, true><<<gExpFF, 256>>>(x, weu, pHE, pEG, nullptr, pOff, pPairtok,
                                            NPAIR, FE, HDIM);
    dim3 gExpDown(HDIM / 128, 16, NE);
    gemm_tc<2, true, false><<<gExpDown, 256>>>(pHE, wed, pPout, nullptr, pPairw, pOff, nullptr,
                                               NPAIR, HDIM, FE);

    // 4) combine
    combine_kernel<<<T_TOK, HDIM / 4>>>(out);
}